// round 7
// baseline (speedup 1.0000x reference)
#include <cuda_runtime.h>
#include <cuda_bf16.h>
#include <math.h>
#include <stdint.h>

#define DIM   256
#define MAXN  100000
#define MAXE  500000

// per-kslice permuted-B block: 32 lanes * (32 atoms * 2 + 4 pad) = 2176 floats
#define LSEG   68
#define KSFL   (32 * LSEG)   // 2176

// ---------------- scratch ---------------------------------------------------
__device__ float g_v[(size_t)MAXN * DIM];     // v[n,:] = W_k @ prev[n,:]
__device__ float g_comb[(size_t)MAXN * DIM];  // unnormalized sum ex * x
__device__ float g_bq[MAXN];                  // b_k . prev[n]
__device__ float g_denom[MAXN];               // sum ex per node
__device__ float g_bperm_v[32 * KSFL];        // wkT in fragment-native layout
__device__ float g_bperm_g[64 * KSFL];        // Wg  in fragment-native layout

// ---------------- helpers ---------------------------------------------------
__device__ __forceinline__ void red_add_v4(float* addr, float a, float b, float c, float d) {
    asm volatile("red.global.add.v4.f32 [%0], {%1,%2,%3,%4};"
                 :: "l"(addr), "f"(a), "f"(b), "f"(c), "f"(d) : "memory");
}
__device__ __forceinline__ void cp_async16(uint32_t saddr, const void* gaddr, int bytes) {
    asm volatile("cp.async.ca.shared.global [%0], [%1], 16, %2;\n"
                 :: "r"(saddr), "l"(gaddr), "r"(bytes));
}
__device__ __forceinline__ void cp_commit() {
    asm volatile("cp.async.commit_group;\n");
}
__device__ __forceinline__ void mma_tf32(float c[4], const uint32_t a[4], uint32_t b0, uint32_t b1) {
    asm volatile(
        "mma.sync.aligned.m16n8k8.row.col.f32.tf32.tf32.f32 "
        "{%0,%1,%2,%3}, {%4,%5,%6,%7}, {%8,%9}, {%0,%1,%2,%3};"
        : "+f"(c[0]), "+f"(c[1]), "+f"(c[2]), "+f"(c[3])
        : "r"(a[0]), "r"(a[1]), "r"(a[2]), "r"(a[3]), "r"(b0), "r"(b1));
}

// ---------------- B permutation ----------------------------------------------
// dst[(ks*32 + lane)*LSEG + atom*2 + slot] = B[ks*8 + (lane&3) + slot*4][atom*8 + (lane>>2)]
// TRANS: B[k][n] = src[n][k] (for wkT built from Wk); else B[k][n] = src[k][n].
template<bool TRANS>
__global__ void k_perm(const float* __restrict__ src, float* __restrict__ dst, int KS) {
    int i = blockIdx.x * blockDim.x + threadIdx.x;      // over KS*32*64
    if (i >= KS * 32 * 64) return;
    int slot = i & 1;
    int atom = (i >> 1) & 31;
    int lane = (i >> 6) & 31;
    int ks   = i >> 11;
    int k = ks * 8 + (lane & 3) + slot * 4;
    int n = atom * 8 + (lane >> 2);
    float v = TRANS ? src[n * DIM + k] : src[k * DIM + n];
    dst[(size_t)(ks * 32 + lane) * LSEG + atom * 2 + slot] = v;
}

// ---------------- fused edge pass --------------------------------------------
__global__ __launch_bounds__(256) void k_edge(const float* __restrict__ x,
                                              const int* __restrict__ idx, int E) {
    int warp = threadIdx.x >> 5, lane = threadIdx.x & 31;
    int e = blockIdx.x * 8 + warp;
    if (e >= E) return;
    int n = __ldg(idx + e);
    const float4* xp = (const float4*)(x + (size_t)e * DIM);
    const float4* vp = (const float4*)(g_v + (size_t)n * DIM);
    float4 a0 = __ldcs(xp + lane);
    float4 a1 = __ldcs(xp + lane + 32);
    float4 b0 = vp[lane], b1 = vp[lane + 32];
    float s = a0.x * b0.x + a0.y * b0.y + a0.z * b0.z + a0.w * b0.w
            + a1.x * b1.x + a1.y * b1.y + a1.z * b1.z + a1.w * b1.w;
    #pragma unroll
    for (int o = 16; o; o >>= 1) s += __shfl_xor_sync(0xffffffffu, s, o);
    float ex = expf((s + g_bq[n]) * 0.0625f);
    if (lane == 0) atomicAdd(&g_denom[n], ex);
    float* cb = g_comb + (size_t)n * DIM;
    red_add_v4(cb + (size_t)lane * 4,        ex * a0.x, ex * a0.y, ex * a0.z, ex * a0.w);
    red_add_v4(cb + (size_t)(lane + 32) * 4, ex * a1.x, ex * a1.y, ex * a1.z, ex * a1.w);
}

// ---------------- tf32 tensor-core GEMM, BM=64 x BN=256 ----------------------
// B operand comes from fragment-native permuted globals -> LDS.128 frag loads.
#define BM 64
#define BN 256
#define BK 16
#define ASTR 20

template<int KTOT, bool GATE>
__global__ __launch_bounds__(256, 2) void k_gemm_tc(const float* __restrict__ Aprev,
                                                    const float* __restrict__ bias,
                                                    float* __restrict__ out, int M) {
    __shared__ float As[2][BM * ASTR];
    __shared__ float Bs[2][2 * KSFL];      // 2 kslices per BK=16 buffer
    __shared__ float bks[DIM];

    const float* BP = GATE ? (const float*)g_bperm_g : (const float*)g_bperm_v;

    const int tid  = threadIdx.x;
    const int lane = tid & 31;
    const int g    = lane >> 2;
    const int tg   = lane & 3;
    const int wid  = tid >> 5;
    const int wR   = (wid & 1) * 32;      // 2 warp-rows x 32
    const int wCat = (wid >> 1) * 8;      // warp col in n-atoms (4 warp-cols x 64)
    const int bm   = blockIdx.y * BM;

    if (!GATE && tid < 64)
        *(float4*)&bks[tid * 4] = *(const float4*)(bias + tid * 4);

    float inv[2][2];
    if (GATE) {
        #pragma unroll
        for (int mi = 0; mi < 2; mi++)
            #pragma unroll
            for (int half = 0; half < 2; half++) {
                int r = bm + wR + mi * 16 + g + half * 8;
                if (r >= M) r = M - 1;
                inv[mi][half] = 1.f / fmaxf(g_denom[r], 1e-9f);
            }
    }

    float c[2][8][4];
    #pragma unroll
    for (int mi = 0; mi < 2; mi++)
        #pragma unroll
        for (int ni = 0; ni < 8; ni++)
            #pragma unroll
            for (int q = 0; q < 4; q++) c[mi][ni][q] = 0.f;

    auto stage = [&](int buf, int it) {
        int k0; const float* asrc; int kb;   // kb = global kslice base (pairs)
        if (GATE) {
            if (it < 16) { k0 = it * 16;        asrc = (const float*)g_comb; kb = 32 + 2 * it; }
            else         { k0 = (it - 16) * 16; asrc = Aprev;                kb = 2 * (it - 16); }
        } else {
            k0 = it * 16; asrc = Aprev; kb = 2 * it;
        }
        {   // A: 64 rows x 16 floats = 256 float4
            int row  = tid >> 2;
            int c4   = (tid & 3) * 4;
            int grow = bm + row;
            int ok   = grow < M;
            int gr   = ok ? grow : (M - 1);
            const float* src = asrc + (size_t)gr * DIM + k0 + c4;
            uint32_t d = (uint32_t)__cvta_generic_to_shared(&As[buf][row * ASTR + c4]);
            cp_async16(d, src, ok ? 16 : 0);
        }
        // B: contiguous copy of 2 kslices (incl. pads) = 1088 float4
        const float* bsrc = BP + (size_t)kb * KSFL;
        #pragma unroll
        for (int j = 0; j < 5; j++) {
            int f = tid + j * 256;
            if (f < 2 * KSFL / 4) {
                uint32_t d = (uint32_t)__cvta_generic_to_shared(&Bs[buf][f * 4]);
                cp_async16(d, bsrc + f * 4, 16);
            }
        }
        cp_commit();
    };

    constexpr int KT = KTOT / BK;
    stage(0, 0);

    float bqacc = 0.f;
    const int bq_row = tid >> 2;
    const int bq_q   = tid & 3;

    #pragma unroll 1
    for (int it = 0; it < KT; it++) {
        if (it + 1 < KT) {
            stage((it + 1) & 1, it + 1);
            asm volatile("cp.async.wait_group 1;\n");
        } else {
            asm volatile("cp.async.wait_group 0;\n");
        }
        __syncthreads();

        const float* Ab = As[it & 1];
        const float* Bb = Bs[it & 1];
        #pragma unroll
        for (int ks = 0; ks < BK; ks += 8) {
            uint32_t a[2][4];
            #pragma unroll
            for (int mi = 0; mi < 2; mi++) {
                int r0 = wR + mi * 16 + g;
                a[mi][0] = __float_as_uint(Ab[(r0)     * ASTR + ks + tg]);
                a[mi][1] = __float_as_uint(Ab[(r0 + 8) * ASTR + ks + tg]);
                a[mi][2] = __float_as_uint(Ab[(r0)     * ASTR + ks + tg + 4]);
                a[mi][3] = __float_as_uint(Ab[(r0 + 8) * ASTR + ks + tg + 4]);
            }
            // B frags: 4 x LDS.128, each covers two n-atoms
            const float* bl = Bb + ((size_t)(ks >> 3) * 32 + lane) * LSEG;
            float4 bf[4];
            #pragma unroll
            for (int nn = 0; nn < 4; nn++)
                bf[nn] = *(const float4*)(bl + (wCat + nn * 2) * 2);
            #pragma unroll
            for (int mi = 0; mi < 2; mi++)
                #pragma unroll
                for (int nn = 0; nn < 4; nn++) {
                    mma_tf32(c[mi][nn * 2 + 0], a[mi],
                             __float_as_uint(bf[nn].x), __float_as_uint(bf[nn].y));
                    mma_tf32(c[mi][nn * 2 + 1], a[mi],
                             __float_as_uint(bf[nn].z), __float_as_uint(bf[nn].w));
                }
        }

        if (!GATE) {
            float s = 0.f;
            #pragma unroll
            for (int j = 0; j < 4; j++)
                s += Ab[bq_row * ASTR + bq_q * 4 + j] * bks[it * 16 + bq_q * 4 + j];
            bqacc += s;
        }

        if (GATE && it == 15) {  // comb phase done: normalize accumulators
            #pragma unroll
            for (int mi = 0; mi < 2; mi++)
                #pragma unroll
                for (int ni = 0; ni < 8; ni++)
                    #pragma unroll
                    for (int q = 0; q < 4; q++)
                        c[mi][ni][q] *= inv[mi][q >> 1];
        }
        __syncthreads();
    }

    if (!GATE) {
        bqacc += __shfl_xor_sync(0xffffffffu, bqacc, 1);
        bqacc += __shfl_xor_sync(0xffffffffu, bqacc, 2);
        if (bq_q == 0 && bm + bq_row < M) g_bq[bm + bq_row] = bqacc;
        if (tid < BM && bm + tid < M) g_denom[bm + tid] = 0.f;   // fused init
    }

    #pragma unroll
    for (int mi = 0; mi < 2; mi++) {
        #pragma unroll
        for (int half = 0; half < 2; half++) {
            int r = bm + wR + mi * 16 + g + half * 8;
            if (r >= M) continue;
            #pragma unroll
            for (int ni = 0; ni < 8; ni++) {
                int cc = wCat * 8 + ni * 8 + tg * 2;
                float v0 = c[mi][ni][half * 2 + 0];
                float v1 = c[mi][ni][half * 2 + 1];
                if (GATE) {
                    float2 bgv = *(const float2*)(bias + cc);
                    float2 pv  = *(const float2*)(Aprev + (size_t)r * DIM + cc);
                    float2 cv  = *(const float2*)(g_comb + (size_t)r * DIM + cc);
                    float iv = inv[mi][half];
                    float g0 = 1.f / (1.f + expf(-(v0 + bgv.x)));
                    float g1 = 1.f / (1.f + expf(-(v1 + bgv.y)));
                    float2 o;
                    o.x = g0 * pv.x + (1.f - g0) * (cv.x * iv);
                    o.y = g1 * pv.y + (1.f - g1) * (cv.y * iv);
                    *(float2*)(out + (size_t)r * DIM + cc) = o;
                } else {
                    *(float2*)(g_v + (size_t)r * DIM + cc) = make_float2(v0, v1);
                    *(float2*)(g_comb + (size_t)r * DIM + cc) = make_float2(0.f, 0.f);
                }
            }
        }
    }
}

// ---------------- launch ------------------------------------------------------
extern "C" void kernel_launch(void* const* d_in, const int* in_sizes, int n_in,
                              void* d_out, int out_size) {
    const float* x    = (const float*)d_in[0];
    const float* prev = (const float*)d_in[1];
    const float* Wk   = (const float*)d_in[2];
    const float* bk   = (const float*)d_in[3];
    const float* Wg   = (const float*)d_in[4];
    const float* bg   = (const float*)d_in[5];
    const int*   idx  = (const int*)d_in[6];
    float* out = (float*)d_out;

    int Dv = in_sizes[3];            // 256
    int E  = in_sizes[0] / Dv;
    int N  = in_sizes[1] / Dv;

    // Build fragment-native B images (wkT from Wk via TRANS; Wg direct).
    float* bpv = nullptr; cudaGetSymbolAddress((void**)&bpv, g_bperm_v);
    float* bpg = nullptr; cudaGetSymbolAddress((void**)&bpg, g_bperm_g);
    k_perm<true ><<<(32 * 2048 + 255) / 256, 256>>>(Wk, bpv, 32);
    k_perm<false><<<(64 * 2048 + 255) / 256, 256>>>(Wg, bpg, 64);

    dim3 gg(1, (N + BM - 1) / BM);
    k_gemm_tc<256, false><<<gg, 256>>>(prev, bk, nullptr, N);
    k_edge<<<(E + 7) / 8, 256>>>(x, idx, E);
    k_gemm_tc<512, true><<<gg, 256>>>(prev, bg, out, N);
}

// round 9
// speedup vs baseline: 1.3412x; 1.3412x over previous
#include <cuda_runtime.h>
#include <cuda_fp16.h>
#include <math.h>
#include <stdint.h>

#define DIM   256
#define MAXN  100000
#define MAXE  500000

// ---------------- scratch ---------------------------------------------------
__device__ float  g_v[(size_t)MAXN * DIM];
__device__ float  g_comb[(size_t)MAXN * DIM];
__device__ float  g_bq[MAXN];
__device__ float  g_denom[MAXN];
__device__ __half g_bh_v[DIM * DIM];        // Wk^T as fp16, [k][n]
__device__ __half g_bh_g[2 * DIM * DIM];    // Wg   as fp16, [k][n] (native layout)

// ---------------- helpers ---------------------------------------------------
__device__ __forceinline__ uint32_t smem_u32(const void* p) {
    uint32_t a;
    asm("{ .reg .u64 t; cvta.to.shared.u64 t, %1; cvt.u32.u64 %0, t; }" : "=r"(a) : "l"(p));
    return a;
}
__device__ __forceinline__ void red_add_v4(float* addr, float a, float b, float c, float d) {
    asm volatile("red.global.add.v4.f32 [%0], {%1,%2,%3,%4};"
                 :: "l"(addr), "f"(a), "f"(b), "f"(c), "f"(d) : "memory");
}
__device__ __forceinline__ void cp_async16(uint32_t saddr, const void* gaddr) {
    asm volatile("cp.async.ca.shared.global [%0], [%1], 16;\n" :: "r"(saddr), "l"(gaddr));
}
__device__ __forceinline__ void cp_commit() {
    asm volatile("cp.async.commit_group;\n");
}
__device__ __forceinline__ void ldsm_x4(uint32_t r[4], uint32_t addr) {
    asm volatile("ldmatrix.sync.aligned.m8n8.x4.shared.b16 {%0,%1,%2,%3}, [%4];"
                 : "=r"(r[0]), "=r"(r[1]), "=r"(r[2]), "=r"(r[3]) : "r"(addr));
}
__device__ __forceinline__ void ldsm_x4_t(uint32_t r[4], uint32_t addr) {
    asm volatile("ldmatrix.sync.aligned.m8n8.x4.trans.shared.b16 {%0,%1,%2,%3}, [%4];"
                 : "=r"(r[0]), "=r"(r[1]), "=r"(r[2]), "=r"(r[3]) : "r"(addr));
}
__device__ __forceinline__ void mma_f16(float c[4], const uint32_t a[4], uint32_t b0, uint32_t b1) {
    asm volatile(
        "mma.sync.aligned.m16n8k16.row.col.f32.f16.f16.f32 "
        "{%0,%1,%2,%3}, {%4,%5,%6,%7}, {%8,%9}, {%0,%1,%2,%3};"
        : "+f"(c[0]), "+f"(c[1]), "+f"(c[2]), "+f"(c[3])
        : "r"(a[0]), "r"(a[1]), "r"(a[2]), "r"(a[3]), "r"(b0), "r"(b1));
}

// ---------------- prep: fp16 B images ----------------------------------------
// g_bh_v[k][n] = Wk[n][k]  (transpose + convert)
__global__ void k_h_wkT(const float* __restrict__ Wk, __half* __restrict__ dst) {
    __shared__ float t[32][33];
    int bk = blockIdx.x * 32, bn = blockIdx.y * 32;
    int tx = threadIdx.x, ty = threadIdx.y;
    #pragma unroll
    for (int i = 0; i < 32; i += 8)
        t[ty + i][tx] = Wk[(bn + ty + i) * DIM + bk + tx];   // src row=n, col=k
    __syncthreads();
    #pragma unroll
    for (int i = 0; i < 32; i += 8)
        dst[(size_t)(bk + ty + i) * DIM + bn + tx] = __float2half(t[tx][ty + i]);
}
// g_bh_g = fp16(Wg), same layout
__global__ void k_h_wg(const float* __restrict__ Wg, __half* __restrict__ dst) {
    int i = blockIdx.x * blockDim.x + threadIdx.x;
    if (i < 2 * DIM * DIM) dst[i] = __float2half(Wg[i]);
}

// ---------------- fused edge pass (n-range split for L2 residency) -----------
__global__ __launch_bounds__(256) void k_edge(const float* __restrict__ x,
                                              const int* __restrict__ idx, int E,
                                              int lo, int hi) {
    int warp = threadIdx.x >> 5, lane = threadIdx.x & 31;
    int e = blockIdx.x * 8 + warp;
    if (e >= E) return;
    int n = __ldg(idx + e);
    if (n < lo || n >= hi) return;
    const float4* xp = (const float4*)(x + (size_t)e * DIM);
    const float4* vp = (const float4*)(g_v + (size_t)n * DIM);
    float4 a0 = __ldcs(xp + lane);
    float4 a1 = __ldcs(xp + lane + 32);
    float4 b0 = vp[lane], b1 = vp[lane + 32];
    float s = a0.x * b0.x + a0.y * b0.y + a0.z * b0.z + a0.w * b0.w
            + a1.x * b1.x + a1.y * b1.y + a1.z * b1.z + a1.w * b1.w;
    #pragma unroll
    for (int o = 16; o; o >>= 1) s += __shfl_xor_sync(0xffffffffu, s, o);
    float ex = expf((s + g_bq[n]) * 0.0625f);
    if (lane == 0) atomicAdd(&g_denom[n], ex);
    float* cb = g_comb + (size_t)n * DIM;
    red_add_v4(cb + (size_t)lane * 4,        ex * a0.x, ex * a0.y, ex * a0.z, ex * a0.w);
    red_add_v4(cb + (size_t)(lane + 32) * 4, ex * a1.x, ex * a1.y, ex * a1.z, ex * a1.w);
}

// ---------------- fp16 tensor-core GEMM, BM=64 x BN=256, BK=32 ---------------
// !GATE: g_v = prev @ WkT; fused bq = bk.prev; zero g_comb/g_denom.
// GATE:  z = (comb*inv) @ Wg[256:] (its 0-7) then += prev @ Wg[:256] (its 8-15);
//        epilogue sigmoid blend -> out.
#define BM 64
#define BN 256
#define BK 32
#define ASTRH 40     // A smem row stride (halves) — LDSM conflict-free
#define BSTRH 264    // B smem row stride (halves) — LDSM conflict-free

template<int KT, bool GATE>
__global__ __launch_bounds__(256, 2) void k_gemm_h(const float* __restrict__ Aprev,
                                                   const float* __restrict__ bias,
                                                   float* __restrict__ out, int M) {
    __shared__ __half As[2][BM * ASTRH];
    __shared__ __half Bs[2][BK * BSTRH];
    __shared__ float  bks[DIM];
    __shared__ float  invs[BM];

    const int tid  = threadIdx.x;
    const int lane = tid & 31;
    const int g    = lane >> 2;
    const int tg   = lane & 3;
    const int wid  = tid >> 5;
    const int wR   = (wid & 1) * 32;     // 2 warp-rows x 32
    const int wCat = (wid >> 1) * 8;     // 4 warp-cols x 8 n-atoms (64 cols)
    const int bm   = blockIdx.x * BM;
    const int lj   = lane >> 3;          // ldmatrix quadrant
    const int lr   = lane & 7;

    if (tid < 64) *(float4*)&bks[tid * 4] = *(const float4*)(bias + tid * 4);
    if (GATE && tid < BM) {
        int r = bm + tid;
        float d = (r < M) ? g_denom[r] : 1.f;
        invs[tid] = 1.f / fmaxf(d, 1e-9f);
    }
    __syncthreads();

    float c[2][8][4];
    #pragma unroll
    for (int mi = 0; mi < 2; mi++)
        #pragma unroll
        for (int ni = 0; ni < 8; ni++)
            #pragma unroll
            for (int q = 0; q < 4; q++) c[mi][ni][q] = 0.f;

    auto ldgA = [&](int it, float4 v[2]) {
        const float* asrc; int k0;
        if (GATE) { if (it < 8) { asrc = (const float*)g_comb; k0 = it * 32; }
                    else        { asrc = Aprev;                k0 = (it - 8) * 32; } }
        else      { asrc = Aprev; k0 = it * 32; }
        #pragma unroll
        for (int j = 0; j < 2; j++) {
            int seg = tid + j * 256;
            int row = seg >> 3, c4 = (seg & 7) * 4;
            int gr = bm + row; if (gr >= M) gr = M - 1;
            v[j] = *(const float4*)(asrc + (size_t)gr * DIM + k0 + c4);
        }
    };
    auto stsA = [&](int it, int buf, const float4 v[2]) {
        bool sc = GATE && (it < 8);
        #pragma unroll
        for (int j = 0; j < 2; j++) {
            int seg = tid + j * 256;
            int row = seg >> 3, c4 = (seg & 7) * 4;
            float4 w = v[j];
            if (sc) { float iv = invs[row]; w.x *= iv; w.y *= iv; w.z *= iv; w.w *= iv; }
            __half2 h0 = __floats2half2_rn(w.x, w.y);
            __half2 h1 = __floats2half2_rn(w.z, w.w);
            uint2 pk = make_uint2(*(uint32_t*)&h0, *(uint32_t*)&h1);
            *(uint2*)&As[buf][row * ASTRH + c4] = pk;
        }
    };
    auto stageB = [&](int it, int buf) {
        const __half* bh = GATE ? (const __half*)g_bh_g : (const __half*)g_bh_v;
        int kb = GATE ? (it < 8 ? 256 + it * 32 : (it - 8) * 32) : it * 32;
        #pragma unroll
        for (int j = 0; j < 4; j++) {
            int seg = tid + j * 256;
            int kr = seg >> 5, c8 = (seg & 31) * 8;
            cp_async16(smem_u32(&Bs[buf][kr * BSTRH + c8]),
                       bh + (size_t)(kb + kr) * DIM + c8);
        }
        cp_commit();
    };

    float4 vA[2], vN[2];
    ldgA(0, vA); stsA(0, 0, vA); stageB(0, 0);

    float bqacc = 0.f;
    const int bq_row = tid >> 2;
    const int bq_q   = tid & 3;

    #pragma unroll 1
    for (int it = 0; it < KT; it++) {
        int buf = it & 1;
        if (it + 1 < KT) {
            ldgA(it + 1, vN);                 // LDG latency hides under compute
            stageB(it + 1, (it + 1) & 1);
            asm volatile("cp.async.wait_group 1;\n" ::: "memory");
        } else {
            asm volatile("cp.async.wait_group 0;\n" ::: "memory");
        }
        __syncthreads();

        const __half* Ab = As[buf];
        const __half* Bb = Bs[buf];
        #pragma unroll
        for (int ks = 0; ks < BK; ks += 16) {
            uint32_t a[2][4];
            #pragma unroll
            for (int mi = 0; mi < 2; mi++) {
                uint32_t ad = smem_u32(&Ab[(wR + mi * 16 + (lj & 1) * 8 + lr) * ASTRH
                                           + ks + (lj >> 1) * 8]);
                ldsm_x4(a[mi], ad);
            }
            #pragma unroll
            for (int nn = 0; nn < 4; nn++) {
                uint32_t b[4];
                uint32_t bd = smem_u32(&Bb[(ks + (lj & 1) * 8 + lr) * BSTRH
                                           + (wCat + nn * 2 + (lj >> 1)) * 8]);
                ldsm_x4_t(b, bd);
                #pragma unroll
                for (int mi = 0; mi < 2; mi++) {
                    mma_f16(c[mi][nn * 2 + 0], a[mi], b[0], b[1]);
                    mma_f16(c[mi][nn * 2 + 1], a[mi], b[2], b[3]);
                }
            }
        }

        if (!GATE) {
            float s = 0.f;
            #pragma unroll
            for (int j = 0; j < 8; j++)
                s += __half2float(Ab[bq_row * ASTRH + bq_q * 8 + j])
                   * bks[it * 32 + bq_q * 8 + j];
            bqacc += s;
        }
        if (GATE && it == 7) { /* comb phase finished — accums already scaled via staging */ }

        if (it + 1 < KT) stsA(it + 1, (it + 1) & 1, vN);
        __syncthreads();
    }

    if (!GATE) {
        bqacc += __shfl_xor_sync(0xffffffffu, bqacc, 1);
        bqacc += __shfl_xor_sync(0xffffffffu, bqacc, 2);
        if (bq_q == 0 && bm + bq_row < M) g_bq[bm + bq_row] = bqacc;
        if (tid < BM && bm + tid < M) g_denom[bm + tid] = 0.f;
    }

    #pragma unroll
    for (int mi = 0; mi < 2; mi++) {
        #pragma unroll
        for (int half = 0; half < 2; half++) {
            int lrow = wR + mi * 16 + g + half * 8;
            int r = bm + lrow;
            if (r >= M) continue;
            #pragma unroll
            for (int ni = 0; ni < 8; ni++) {
                int cc = wCat * 8 + ni * 8 + tg * 2;
                float v0 = c[mi][ni][half * 2 + 0];
                float v1 = c[mi][ni][half * 2 + 1];
                if (GATE) {
                    float2 pv = *(const float2*)(Aprev + (size_t)r * DIM + cc);
                    float2 cv = *(const float2*)(g_comb + (size_t)r * DIM + cc);
                    float iv = invs[lrow];
                    float g0 = 1.f / (1.f + expf(-(v0 + bks[cc])));
                    float g1 = 1.f / (1.f + expf(-(v1 + bks[cc + 1])));
                    float2 o;
                    o.x = g0 * pv.x + (1.f - g0) * (cv.x * iv);
                    o.y = g1 * pv.y + (1.f - g1) * (cv.y * iv);
                    *(float2*)(out + (size_t)r * DIM + cc) = o;
                } else {
                    *(float2*)(g_v + (size_t)r * DIM + cc) = make_float2(v0, v1);
                    *(float2*)(g_comb + (size_t)r * DIM + cc) = make_float2(0.f, 0.f);
                }
            }
        }
    }
}

// ---------------- launch ------------------------------------------------------
extern "C" void kernel_launch(void* const* d_in, const int* in_sizes, int n_in,
                              void* d_out, int out_size) {
    const float* x    = (const float*)d_in[0];
    const float* prev = (const float*)d_in[1];
    const float* Wk   = (const float*)d_in[2];
    const float* bk   = (const float*)d_in[3];
    const float* Wg   = (const float*)d_in[4];
    const float* bg   = (const float*)d_in[5];
    const int*   idx  = (const int*)d_in[6];
    float* out = (float*)d_out;

    int Dv = in_sizes[3];            // 256
    int E  = in_sizes[0] / Dv;
    int N  = in_sizes[1] / Dv;

    __half* bhv = nullptr; cudaGetSymbolAddress((void**)&bhv, g_bh_v);
    __half* bhg = nullptr; cudaGetSymbolAddress((void**)&bhg, g_bh_g);
    k_h_wkT<<<dim3(8, 8), dim3(32, 8)>>>(Wk, bhv);
    k_h_wg<<<(2 * DIM * DIM + 255) / 256, 256>>>(Wg, bhg);

    int gb = (N + BM - 1) / BM;
    k_gemm_h<8, false><<<gb, 256>>>(prev, bk, nullptr, N);

    int Nh = N / 2;
    int eg = (E + 7) / 8;
    k_edge<<<eg, 256>>>(x, idx, E, 0, Nh);
    k_edge<<<eg, 256>>>(x, idx, E, Nh, N);

    k_gemm_h<16, true><<<gb, 256>>>(prev, bg, out, N);
}